// round 1
// baseline (speedup 1.0000x reference)
#include <cuda_runtime.h>
#include <cstdint>

#define ROWS 32
#define THREADS 256
#define NLAYERS 25
#define KOUT 50
#define FW 1266
#define XS 1268           // padded x row stride in floats (5072 B, 16B-aligned)
#define JC 32             // j-chunk of weights staged per step
#define JCP 36            // padded chunk stride (144 B: 16B-aligned, conflict-free)

__device__ __forceinline__ void fma2(unsigned long long &d,
                                     const unsigned long long a,
                                     const unsigned long long b) {
    // packed fp32x2 FMA: 2 MACs per issue slot (ptxas never emits this from C++)
    asm volatile("fma.rn.f32x2 %0, %1, %2, %0;" : "+l"(d) : "l"(a), "l"(b));
}

__global__ void __launch_bounds__(THREADS, 1) value_model_kernel(
    const float* __restrict__ state,
    const float* __restrict__ Ws,
    const float* __restrict__ bs,
    const float* __restrict__ Wout,
    const float* __restrict__ bout,
    float* __restrict__ out)
{
    extern __shared__ float sm[];
    float* xs = sm;                  // [ROWS][XS] growing activations
    float* wb = sm + ROWS * XS;      // [2][KOUT][JCP] double-buffered W chunk

    const int tid  = threadIdx.x;
    const int lane = tid & 31;
    const int wid  = tid >> 5;
    const int r0   = wid * 4;        // 8 warps x 4 rows = 32 rows
    const int k0   = lane;           // output col slot 0
    const int k1   = lane + 32;      // output col slot 1 (active for lane<18)
    const bool hk1 = (k1 < KOUT);
    const int cta  = blockIdx.x;

    // ---- load initial state (32 rows x 16 features) ----
    for (int idx = tid; idx < ROWS * 16; idx += THREADS) {
        int r = idx >> 4, j = idx & 15;
        xs[r * XS + j] = state[(cta * ROWS + r) * 16 + j];
    }
    __syncthreads();

    int width = 16;
    for (int layer = 0; layer < NLAYERS; layer++) {
        const float* W = Ws + (size_t)layer * KOUT * FW;
        const int nc = (width + JC - 1) / JC;

        // stage chunk 0 into buffer 0
        {
            float* dst = wb;
            for (int idx = tid; idx < KOUT * (JC / 2); idx += THREADS) {
                int k = idx >> 4, p = idx & 15;
                int j = p * 2;
                if (j < width) {
                    uint32_t sa = (uint32_t)__cvta_generic_to_shared(&dst[k * JCP + p * 2]);
                    asm volatile("cp.async.ca.shared.global [%0], [%1], 8;"
                                 :: "r"(sa), "l"(W + (size_t)k * FW + j));
                }
            }
            asm volatile("cp.async.commit_group;");
        }

        // accumulators: [row][kslot][pair-half], each is a packed f32x2 partial sum
        unsigned long long acc[4][2][2];
        #pragma unroll
        for (int t = 0; t < 4; t++)
            #pragma unroll
            for (int s = 0; s < 2; s++)
                #pragma unroll
                for (int h = 0; h < 2; h++) acc[t][s][h] = 0ULL;

        for (int c = 0; c < nc; c++) {
            // prefetch chunk c+1 (buffer parity (c+1)&1 was released by the
            // __syncthreads at the end of iteration c-1)
            if (c + 1 < nc) {
                float* dst = wb + ((c + 1) & 1) * KOUT * JCP;
                const int jb = (c + 1) * JC;
                for (int idx = tid; idx < KOUT * (JC / 2); idx += THREADS) {
                    int k = idx >> 4, p = idx & 15;
                    int j = jb + p * 2;
                    if (j < width) {
                        uint32_t sa = (uint32_t)__cvta_generic_to_shared(&dst[k * JCP + p * 2]);
                        asm volatile("cp.async.ca.shared.global [%0], [%1], 8;"
                                     :: "r"(sa), "l"(W + (size_t)k * FW + j));
                    }
                }
                asm volatile("cp.async.commit_group;");
                asm volatile("cp.async.wait_group 1;");   // chunk c has landed
            } else {
                asm volatile("cp.async.wait_group 0;");
            }
            __syncthreads();

            const float* wbc  = wb + (c & 1) * KOUT * JCP;
            const int jbase   = c * JC;
            const int jlim    = min(JC, width - jbase);
            const int jmain   = jlim & ~3;

            for (int jj = 0; jj < jmain; jj += 4) {
                ulonglong2 w0 = *(const ulonglong2*)(wbc + k0 * JCP + jj);
                ulonglong2 w1 = hk1 ? *(const ulonglong2*)(wbc + k1 * JCP + jj)
                                    : make_ulonglong2(0ULL, 0ULL);
                #pragma unroll
                for (int t = 0; t < 4; t++) {
                    ulonglong2 xv = *(const ulonglong2*)(xs + (r0 + t) * XS + jbase + jj);
                    fma2(acc[t][0][0], xv.x, w0.x);
                    fma2(acc[t][0][1], xv.y, w0.y);
                    fma2(acc[t][1][0], xv.x, w1.x);
                    fma2(acc[t][1][1], xv.y, w1.y);
                }
            }
            if (jmain < jlim) {   // width % 4 == 2 tail: one packed pair
                unsigned long long w0 = *(const unsigned long long*)(wbc + k0 * JCP + jmain);
                unsigned long long w1 = hk1 ? *(const unsigned long long*)(wbc + k1 * JCP + jmain)
                                            : 0ULL;
                #pragma unroll
                for (int t = 0; t < 4; t++) {
                    unsigned long long xv =
                        *(const unsigned long long*)(xs + (r0 + t) * XS + jbase + jmain);
                    fma2(acc[t][0][0], xv, w0);
                    fma2(acc[t][1][0], xv, w1);
                }
            }
            __syncthreads();   // releases buffer (c&1) for prefetch of chunk c+2
        }

        // ---- epilogue: reduce halves, bias, leaky-relu, append to x ----
        const float b0 = bs[layer * KOUT + k0];
        const float b1 = hk1 ? bs[layer * KOUT + k1] : 0.f;
        #pragma unroll
        for (int t = 0; t < 4; t++) {
            float2 a0 = *(float2*)&acc[t][0][0];
            float2 a1 = *(float2*)&acc[t][0][1];
            float y = (a0.x + a0.y) + (a1.x + a1.y) + b0;
            y = (y > 0.f) ? y : 0.01f * y;
            xs[(r0 + t) * XS + width + k0] = y;
            if (hk1) {
                float2 c0 = *(float2*)&acc[t][1][0];
                float2 c1 = *(float2*)&acc[t][1][1];
                float z = (c0.x + c0.y) + (c1.x + c1.y) + b1;
                z = (z > 0.f) ? z : 0.01f * z;
                xs[(r0 + t) * XS + width + k1] = z;
            }
        }
        width += KOUT;
        __syncthreads();
    }

    // ---- final projection: out[r] = x[r] . Wout + bout ----
    #pragma unroll
    for (int t = 0; t < 4; t++) {
        const int r = r0 + t;
        float s = 0.f;
        for (int j = lane; j < FW; j += 32)
            s += xs[r * XS + j] * Wout[j];
        #pragma unroll
        for (int o = 16; o; o >>= 1) s += __shfl_xor_sync(0xffffffffu, s, o);
        if (lane == 0) out[cta * ROWS + r] = s + bout[0];
    }
}

extern "C" void kernel_launch(void* const* d_in, const int* in_sizes, int n_in,
                              void* d_out, int out_size) {
    const float* state = (const float*)d_in[0];
    const float* Ws    = (const float*)d_in[1];
    const float* bs    = (const float*)d_in[2];
    const float* Wout  = (const float*)d_in[3];
    const float* bout  = (const float*)d_in[4];
    float* out = (float*)d_out;

    const int B = in_sizes[0] / 16;              // 32768
    const size_t smem = (size_t)(ROWS * XS + 2 * KOUT * JCP) * sizeof(float); // ~176.7 KB
    cudaFuncSetAttribute(value_model_kernel,
                         cudaFuncAttributeMaxDynamicSharedMemorySize, (int)smem);
    value_model_kernel<<<B / ROWS, THREADS, smem>>>(state, Ws, bs, Wout, bout, out);
}

// round 2
// speedup vs baseline: 2.8469x; 2.8469x over previous
#include <cuda_runtime.h>
#include <cuda_bf16.h>
#include <cstdint>

#define NLAYERS 25
#define KOUT 50
#define FW 1266
#define ROWS 32
#define THREADS 256
#define MAXKS 76            // max k16 steps (width up to 1216 for last layer GEMM)
#define RSE 1288            // A-plane row stride in bf16 elems (2576B: 16B-aligned, ldmatrix conflict-free)
#define A_PLANE_BYTES (ROWS * RSE * 2)          // 82432
#define ALO_OFF A_PLANE_BYTES
#define WOFF (2 * A_PLANE_BYTES)                // 164864, 16B aligned
#define WBUF_BYTES 16384                        // 4 k16-steps of staged W fragments
#define SMEM_TOTAL (WOFF + 2 * WBUF_BYTES)      // 197632

// Staged W fragments: [layer][ks][nt(8)][plane(2)][lane(32)][reg(2)] packed bf16x2 words
#define WFRAG_WORDS (NLAYERS * MAXKS * 8 * 2 * 32 * 2)   // 1,945,600 words = 7.78 MB
__device__ uint32_t g_wfrag[WFRAG_WORDS];

__device__ __forceinline__ uint32_t pack2(float a, float b) {
    uint32_t lo = (uint32_t)__bfloat16_as_ushort(__float2bfloat16_rn(a));
    uint32_t hi = (uint32_t)__bfloat16_as_ushort(__float2bfloat16_rn(b));
    return lo | (hi << 16);
}

// ---- prekernel: fp32 W -> fragment-ordered bf16 hi/lo planes ----
__global__ void stage_w_kernel(const float* __restrict__ Ws) {
    int i = blockIdx.x * THREADS + threadIdx.x;
    if (i >= WFRAG_WORDS) return;
    int w = i;
    int reg   = w & 1;  w >>= 1;
    int ln    = w & 31; w >>= 5;
    int plane = w & 1;  w >>= 1;
    int nt    = w & 7;  w >>= 3;
    int ks    = w % MAXKS;
    int layer = w / MAXKS;
    int n = nt * 8 + (ln >> 2);
    int k = ks * 16 + ((ln & 3) << 1) + reg * 8;
    float w0 = 0.f, w1 = 0.f;
    if (n < KOUT) {
        const float* p = Ws + ((size_t)layer * KOUT + n) * FW + k;
        w0 = p[0]; w1 = p[1];
    }
    uint32_t word;
    if (plane == 0) {
        word = pack2(w0, w1);
    } else {
        float h0 = __bfloat162float(__float2bfloat16_rn(w0));
        float h1 = __bfloat162float(__float2bfloat16_rn(w1));
        word = pack2(w0 - h0, w1 - h1);
    }
    g_wfrag[i] = word;
}

#define MMA(d, a, b0_, b1_) \
    asm volatile("mma.sync.aligned.m16n8k16.row.col.f32.bf16.bf16.f32 " \
        "{%0,%1,%2,%3},{%4,%5,%6,%7},{%8,%9},{%0,%1,%2,%3};" \
        : "+f"(d[0]), "+f"(d[1]), "+f"(d[2]), "+f"(d[3]) \
        : "r"(a[0]), "r"(a[1]), "r"(a[2]), "r"(a[3]), "r"(b0_), "r"(b1_))

#define LDSM4(r, addr) \
    asm volatile("ldmatrix.sync.aligned.m8n8.x4.shared.b16 {%0,%1,%2,%3}, [%4];" \
        : "=r"(r[0]), "=r"(r[1]), "=r"(r[2]), "=r"(r[3]) : "r"(addr))

__device__ __forceinline__ void cp16(uint32_t dst, const void* src) {
    asm volatile("cp.async.cg.shared.global [%0], [%1], 16;" :: "r"(dst), "l"(src));
}

__global__ void __launch_bounds__(THREADS, 1) value_model_mma_kernel(
    const float* __restrict__ state,
    const float* __restrict__ bs,
    const float* __restrict__ Wout,
    const float* __restrict__ bout,
    float* __restrict__ out)
{
    extern __shared__ char smraw[];
    __nv_bfloat16* Ahi = (__nv_bfloat16*)smraw;
    __nv_bfloat16* Alo = (__nv_bfloat16*)(smraw + ALO_OFF);
    const uint32_t sm_u32 = (uint32_t)__cvta_generic_to_shared(smraw);

    const int tid  = threadIdx.x;
    const int lane = tid & 31;
    const int wid  = tid >> 5;
    const int cta  = blockIdx.x;
    const int r0m  = (wid & 1) * 16;    // m-tile base row
    const int ng   = wid >> 1;          // n-group (n16)

    // ---- zero both A planes ----
    uint32_t* az = (uint32_t*)smraw;
    for (int i = tid; i < (2 * A_PLANE_BYTES) / 4; i += THREADS) az[i] = 0u;
    __syncthreads();

    // ---- load initial state (32 x 16) as hi/lo planes ----
    for (int idx = tid; idx < ROWS * 16; idx += THREADS) {
        int r = idx >> 4, j = idx & 15;
        float v = state[(cta * ROWS + r) * 16 + j];
        __nv_bfloat16 h = __float2bfloat16_rn(v);
        Ahi[r * RSE + j] = h;
        Alo[r * RSE + j] = __float2bfloat16_rn(v - __bfloat162float(h));
    }
    __syncthreads();

    // per-thread ldmatrix base address (Ahi plane, this warp's m-tile)
    const uint32_t abase = sm_u32 + (uint32_t)((r0m + (lane & 15)) * RSE) * 2u
                                  + (uint32_t)(lane >> 4) * 16u;
    const uint32_t wsm   = sm_u32 + WOFF;

    int width = 16;
    for (int l = 0; l < NLAYERS; l++) {
        const int nks = (width + 15) >> 4;
        const int nc  = (nks + 3) >> 2;

        float acc1[2][4] = {}, acc2[2][4] = {};

        // prologue: stage chunk 0
        {
            const char* src = (const char*)g_wfrag + (size_t)(l * MAXKS) * 4096 + tid * 64;
            uint32_t dst = wsm + tid * 64;
            #pragma unroll
            for (int i = 0; i < 4; i++) cp16(dst + i * 16, src + i * 16);
            asm volatile("cp.async.commit_group;");
        }

        for (int c = 0; c < nc; c++) {
            if (c + 1 < nc) {
                const char* src = (const char*)g_wfrag
                                + (size_t)(l * MAXKS + (c + 1) * 4) * 4096 + tid * 64;
                uint32_t dst = wsm + (((c + 1) & 1) ? WBUF_BYTES : 0) + tid * 64;
                #pragma unroll
                for (int i = 0; i < 4; i++) cp16(dst + i * 16, src + i * 16);
                asm volatile("cp.async.commit_group;");
                asm volatile("cp.async.wait_group 1;");
            } else {
                asm volatile("cp.async.wait_group 0;");
            }
            __syncthreads();

            const uint32_t* wb = (const uint32_t*)(smraw + WOFF + ((c & 1) ? WBUF_BYTES : 0));
            const int ksn = min(4, nks - c * 4);

            for (int ksl = 0; ksl < ksn; ksl++) {
                const int ks = c * 4 + ksl;
                uint32_t ah[4], al[4];
                const uint32_t aaddr = abase + (uint32_t)ks * 32u;
                LDSM4(ah, aaddr);
                LDSM4(al, aaddr + (uint32_t)ALO_OFF);
                const uint32_t* wks = wb + ksl * 1024;   // 8 nt * 2 planes * 64 words
                #pragma unroll
                for (int t = 0; t < 2; t++) {
                    const uint32_t* p = wks + ((ng * 2 + t) * 2) * 64 + lane * 2;
                    uint2 bh = *(const uint2*)p;
                    uint2 bl = *(const uint2*)(p + 64);
                    MMA(acc1[t], ah, bh.x, bh.y);
                    MMA(acc2[t], al, bh.x, bh.y);
                    MMA(acc2[t], ah, bl.x, bl.y);
                }
            }
            __syncthreads();
        }

        // ---- epilogue: bias + leaky_relu, append as hi/lo bf16 ----
        #pragma unroll
        for (int t = 0; t < 2; t++) {
            const int n0 = ng * 16 + t * 8 + ((lane & 3) << 1);
            const int rA = r0m + (lane >> 2);
            #pragma unroll
            for (int half = 0; half < 2; half++) {   // half 0: cols n0; half 1: n0+1
                const int n = n0 + half;
                if (n < KOUT) {
                    const float bz = bs[l * KOUT + n];
                    #pragma unroll
                    for (int rr = 0; rr < 2; rr++) {  // rr 0: row rA; 1: row rA+8
                        const int ci = rr * 2 + half;
                        float y = acc1[t][ci] + acc2[t][ci] + bz;
                        y = (y > 0.f) ? y : 0.01f * y;
                        const int r = rA + rr * 8;
                        __nv_bfloat16 h = __float2bfloat16_rn(y);
                        Ahi[r * RSE + width + n] = h;
                        Alo[r * RSE + width + n] =
                            __float2bfloat16_rn(y - __bfloat162float(h));
                    }
                }
            }
        }
        width += KOUT;
        __syncthreads();
    }

    // ---- final projection: out[r] = (hi+lo) . Wout + bout ----
    #pragma unroll
    for (int t = 0; t < 4; t++) {
        const int r = wid * 4 + t;
        float s = 0.f;
        for (int j = lane; j < FW; j += 32)
            s += (__bfloat162float(Ahi[r * RSE + j]) +
                  __bfloat162float(Alo[r * RSE + j])) * Wout[j];
        #pragma unroll
        for (int o = 16; o; o >>= 1) s += __shfl_xor_sync(0xffffffffu, s, o);
        if (lane == 0) out[cta * ROWS + r] = s + bout[0];
    }
}

extern "C" void kernel_launch(void* const* d_in, const int* in_sizes, int n_in,
                              void* d_out, int out_size) {
    const float* state = (const float*)d_in[0];
    const float* Ws    = (const float*)d_in[1];
    const float* bs    = (const float*)d_in[2];
    const float* Wout  = (const float*)d_in[3];
    const float* bout  = (const float*)d_in[4];
    float* out = (float*)d_out;

    const int B = in_sizes[0] / 16;   // 32768

    stage_w_kernel<<<(WFRAG_WORDS + THREADS - 1) / THREADS, THREADS>>>(Ws);

    cudaFuncSetAttribute(value_model_mma_kernel,
                         cudaFuncAttributeMaxDynamicSharedMemorySize, SMEM_TOTAL);
    value_model_mma_kernel<<<B / ROWS, THREADS, SMEM_TOTAL>>>(state, bs, Wout, bout, out);
}

// round 3
// speedup vs baseline: 3.2054x; 1.1259x over previous
#include <cuda_runtime.h>
#include <cuda_bf16.h>
#include <cstdint>

#define NLAYERS 25
#define KOUT 50
#define FW 1266
#define ROWS 32
#define THREADS 512
#define MAXKS 76            // max k16 steps (width up to 1216 for last layer GEMM)
#define RSE 1288            // A-plane row stride in bf16 elems (2576B: 16B-aligned)
#define A_PLANE_BYTES (ROWS * RSE * 2)          // 82432
#define ALO_OFF A_PLANE_BYTES
#define WOFF (2 * A_PLANE_BYTES)                // 164864, 16B aligned
#define WBUF_BYTES 16384                        // 4 k16-steps of staged W fragments
#define SMEM_TOTAL (WOFF + 2 * WBUF_BYTES)      // 197632

// Staged W fragments: [layer][ks][nt(8)][lane(32)][word(4)]
//   word 0,1 = Bhi regs (k+0..7, k+8..15), word 2,3 = Blo regs -> one LDS.128
#define WFRAG_WORDS (NLAYERS * MAXKS * 8 * 32 * 4)   // 1,945,600 words = 7.78 MB
__device__ uint32_t g_wfrag[WFRAG_WORDS];

__device__ __forceinline__ uint32_t pack2(float a, float b) {
    uint32_t lo = (uint32_t)__bfloat16_as_ushort(__float2bfloat16_rn(a));
    uint32_t hi = (uint32_t)__bfloat16_as_ushort(__float2bfloat16_rn(b));
    return lo | (hi << 16);
}

// ---- prekernel: fp32 W -> fragment-ordered bf16 hi/lo packed quads ----
__global__ void stage_w_kernel(const float* __restrict__ Ws) {
    int i = blockIdx.x * blockDim.x + threadIdx.x;
    if (i >= WFRAG_WORDS) return;
    int w = i;
    int word  = w & 3;  w >>= 2;
    int ln    = w & 31; w >>= 5;
    int nt    = w & 7;  w >>= 3;
    int ks    = w % MAXKS;
    int layer = w / MAXKS;
    int plane = word >> 1;
    int reg   = word & 1;
    int n = nt * 8 + (ln >> 2);
    int k = ks * 16 + ((ln & 3) << 1) + reg * 8;
    float w0 = 0.f, w1 = 0.f;
    if (n < KOUT) {
        const float* p = Ws + ((size_t)layer * KOUT + n) * FW + k;
        w0 = p[0]; w1 = p[1];
    }
    uint32_t v;
    if (plane == 0) {
        v = pack2(w0, w1);
    } else {
        float h0 = __bfloat162float(__float2bfloat16_rn(w0));
        float h1 = __bfloat162float(__float2bfloat16_rn(w1));
        v = pack2(w0 - h0, w1 - h1);
    }
    g_wfrag[i] = v;
}

#define MMA(d, a, b0_, b1_) \
    asm volatile("mma.sync.aligned.m16n8k16.row.col.f32.bf16.bf16.f32 " \
        "{%0,%1,%2,%3},{%4,%5,%6,%7},{%8,%9},{%0,%1,%2,%3};" \
        : "+f"(d[0]), "+f"(d[1]), "+f"(d[2]), "+f"(d[3]) \
        : "r"(a[0]), "r"(a[1]), "r"(a[2]), "r"(a[3]), "r"(b0_), "r"(b1_))

#define LDSM4(r, addr) \
    asm volatile("ldmatrix.sync.aligned.m8n8.x4.shared.b16 {%0,%1,%2,%3}, [%4];" \
        : "=r"(r[0]), "=r"(r[1]), "=r"(r[2]), "=r"(r[3]) : "r"(addr))

__device__ __forceinline__ void cp16(uint32_t dst, const void* src) {
    asm volatile("cp.async.cg.shared.global [%0], [%1], 16;" :: "r"(dst), "l"(src));
}

__global__ void __launch_bounds__(THREADS, 1) value_model_mma_kernel(
    const float* __restrict__ state,
    const float* __restrict__ bs,
    const float* __restrict__ Wout,
    const float* __restrict__ bout,
    float* __restrict__ out)
{
    extern __shared__ char smraw[];
    __nv_bfloat16* Ahi = (__nv_bfloat16*)smraw;
    __nv_bfloat16* Alo = (__nv_bfloat16*)(smraw + ALO_OFF);
    const uint32_t sm_u32 = (uint32_t)__cvta_generic_to_shared(smraw);

    const int tid  = threadIdx.x;
    const int lane = tid & 31;
    const int wid  = tid >> 5;
    const int cta  = blockIdx.x;
    const int m    = wid & 1;          // m-tile (rows m*16 .. m*16+15)
    const int ng   = (wid >> 1) & 3;   // n16 group
    const int kg   = wid >> 3;         // k-group (0/1): split of 4 ks per chunk
    const int r0m  = m * 16;
    const int mn   = wid & 7;          // (m,ng) pair id, shared by both k-groups

    // ---- zero both A planes ----
    uint32_t* az = (uint32_t*)smraw;
    for (int i = tid; i < (2 * A_PLANE_BYTES) / 4; i += THREADS) az[i] = 0u;
    __syncthreads();

    // ---- load initial state (32 x 16) as hi/lo planes ----
    if (tid < ROWS * 16) {
        int r = tid >> 4, j = tid & 15;
        float v = state[(cta * ROWS + r) * 16 + j];
        __nv_bfloat16 h = __float2bfloat16_rn(v);
        Ahi[r * RSE + j] = h;
        Alo[r * RSE + j] = __float2bfloat16_rn(v - __bfloat162float(h));
    }
    __syncthreads();

    // ldmatrix base address (this warp's m-tile, hi plane)
    const uint32_t abase = sm_u32 + (uint32_t)((r0m + (lane & 15)) * RSE) * 2u
                                  + (uint32_t)(lane >> 4) * 16u;
    const uint32_t wsm   = sm_u32 + WOFF;
    float* scratch = (float*)(smraw + WOFF);   // overlays W buffers (dead at epilogue)

    int width = 16;
    for (int l = 0; l < NLAYERS; l++) {
        const int nks = (width + 15) >> 4;
        const int nc  = (nks + 3) >> 2;

        float acc1[2][4] = {}, acc2[2][4] = {};

        // prologue: stage chunk 0 (16KB: 512 threads x 32B)
        {
            const char* src = (const char*)g_wfrag + (size_t)(l * MAXKS) * 4096 + tid * 32;
            uint32_t dst = wsm + tid * 32;
            cp16(dst, src);
            cp16(dst + 16, src + 16);
            asm volatile("cp.async.commit_group;");
        }

        for (int c = 0; c < nc; c++) {
            if (c + 1 < nc) {
                const char* src = (const char*)g_wfrag
                                + (size_t)(l * MAXKS + (c + 1) * 4) * 4096 + tid * 32;
                uint32_t dst = wsm + (((c + 1) & 1) ? WBUF_BYTES : 0) + tid * 32;
                cp16(dst, src);
                cp16(dst + 16, src + 16);
                asm volatile("cp.async.commit_group;");
                asm volatile("cp.async.wait_group 1;");
            } else {
                asm volatile("cp.async.wait_group 0;");
            }
            __syncthreads();

            const uint32_t* wb = (const uint32_t*)(smraw + WOFF + ((c & 1) ? WBUF_BYTES : 0));
            const int ksn = min(4, nks - c * 4);

            #pragma unroll
            for (int i = 0; i < 2; i++) {
                const int ksl = kg * 2 + i;
                if (ksl < ksn) {
                    const int ks = c * 4 + ksl;
                    uint32_t ah[4], al[4];
                    const uint32_t aaddr = abase + (uint32_t)ks * 32u;
                    LDSM4(ah, aaddr);
                    LDSM4(al, aaddr + (uint32_t)ALO_OFF);
                    const uint32_t* wks = wb + ksl * 1024;   // 8 nt * 128 words
                    #pragma unroll
                    for (int t = 0; t < 2; t++) {
                        uint4 b = *(const uint4*)(wks + (ng * 2 + t) * 128 + lane * 4);
                        MMA(acc1[t], ah, b.x, b.y);
                        MMA(acc2[t], al, b.x, b.y);
                        MMA(acc2[t], ah, b.z, b.w);
                    }
                }
            }
            __syncthreads();
        }

        // ---- epilogue: cross-k reduce via smem, bias + leaky_relu, append ----
        if (kg == 1) {
            #pragma unroll
            for (int t = 0; t < 2; t++)
                #pragma unroll
                for (int i = 0; i < 4; i++)
                    scratch[mn * 256 + lane * 8 + t * 4 + i] = acc1[t][i] + acc2[t][i];
        }
        __syncthreads();
        if (kg == 0) {
            #pragma unroll
            for (int t = 0; t < 2; t++) {
                const int n0 = ng * 16 + t * 8 + ((lane & 3) << 1);
                const int rA = r0m + (lane >> 2);
                #pragma unroll
                for (int half = 0; half < 2; half++) {
                    const int n = n0 + half;
                    if (n < KOUT) {
                        const float bz = bs[l * KOUT + n];
                        #pragma unroll
                        for (int rr = 0; rr < 2; rr++) {
                            const int ci = rr * 2 + half;
                            float y = acc1[t][ci] + acc2[t][ci]
                                    + scratch[mn * 256 + lane * 8 + t * 4 + ci] + bz;
                            y = (y > 0.f) ? y : 0.01f * y;
                            const int r = rA + rr * 8;
                            __nv_bfloat16 h = __float2bfloat16_rn(y);
                            Ahi[r * RSE + width + n] = h;
                            Alo[r * RSE + width + n] =
                                __float2bfloat16_rn(y - __bfloat162float(h));
                        }
                    }
                }
            }
        }
        width += KOUT;
        __syncthreads();
    }

    // ---- final projection: out[r] = (hi+lo) . Wout + bout ----
    #pragma unroll
    for (int t = 0; t < 2; t++) {
        const int r = wid * 2 + t;
        float s = 0.f;
        for (int j = lane; j < FW; j += 32)
            s += (__bfloat162float(Ahi[r * RSE + j]) +
                  __bfloat162float(Alo[r * RSE + j])) * Wout[j];
        #pragma unroll
        for (int o = 16; o; o >>= 1) s += __shfl_xor_sync(0xffffffffu, s, o);
        if (lane == 0) out[cta * ROWS + r] = s + bout[0];
    }
}

extern "C" void kernel_launch(void* const* d_in, const int* in_sizes, int n_in,
                              void* d_out, int out_size) {
    const float* state = (const float*)d_in[0];
    const float* Ws    = (const float*)d_in[1];
    const float* bs    = (const float*)d_in[2];
    const float* Wout  = (const float*)d_in[3];
    const float* bout  = (const float*)d_in[4];
    float* out = (float*)d_out;

    const int B = in_sizes[0] / 16;   // 32768

    stage_w_kernel<<<(WFRAG_WORDS + 255) / 256, 256>>>(Ws);

    cudaFuncSetAttribute(value_model_mma_kernel,
                         cudaFuncAttributeMaxDynamicSharedMemorySize, SMEM_TOTAL);
    value_model_mma_kernel<<<B / ROWS, THREADS, SMEM_TOTAL>>>(state, bs, Wout, bout, out);
}

// round 4
// speedup vs baseline: 5.4848x; 1.7111x over previous
#include <cuda_runtime.h>
#include <cuda_fp16.h>
#include <cstdint>

#define NLAYERS 25
#define KOUT 50
#define FW 1266
#define ROWS 64
#define THREADS 512
#define MAXKS 76
#define NT 7
#define RSE 1272                         // fp16 elems/row: 2544B, 16B-aligned, 2544%128=112 -> conflict-free
#define A_BYTES (ROWS * RSE * 2)         // 162816
#define WOFF A_BYTES
#define KSB 3584                         // bytes per ks block: 7 nt * 32 lanes * 16B
#define WBUF (8 * KSB)                   // 28672 (8-ks chunk)
#define SMEM_TOTAL (WOFF + 2 * WBUF)     // 220160

// W fragments: [layer][ks(76)][nt(7)][lane(32)][word(4)]; word = {bhi_r0,bhi_r1,blo_r0,blo_r1}
#define WFRAG_WORDS (NLAYERS * MAXKS * NT * 32 * 4)   // 1,702,400 (6.81 MB)
__device__ uint32_t g_wfrag[WFRAG_WORDS];

__device__ __forceinline__ uint32_t packh2(__half a, __half b) {
    return (uint32_t)__half_as_ushort(a) | ((uint32_t)__half_as_ushort(b) << 16);
}

// ---- prekernel: fp32 W -> fragment-ordered fp16 hi/lo quads ----
__global__ void stage_w_kernel(const float* __restrict__ Ws) {
    int i = blockIdx.x * blockDim.x + threadIdx.x;
    if (i >= WFRAG_WORDS) return;
    int w = i;
    int word = w & 3;  w >>= 2;
    int ln   = w & 31; w >>= 5;
    int nt   = w % NT; w /= NT;
    int ks   = w % MAXKS;
    int layer = w / MAXKS;
    int plane = word >> 1;
    int reg   = word & 1;
    int n = nt * 8 + (ln >> 2);
    int k = ks * 16 + ((ln & 3) << 1) + reg * 8;
    float w0 = 0.f, w1 = 0.f;
    if (n < KOUT) {
        const float* p = Ws + ((size_t)layer * KOUT + n) * FW + k;
        w0 = p[0]; w1 = p[1];
    }
    uint32_t v;
    if (plane == 0) {
        v = packh2(__float2half_rn(w0), __float2half_rn(w1));
    } else {
        __half h0 = __float2half_rn(w0), h1 = __float2half_rn(w1);
        v = packh2(__float2half_rn(w0 - __half2float(h0)),
                   __float2half_rn(w1 - __half2float(h1)));
    }
    g_wfrag[i] = v;
}

#define MMA(d, a, b0_, b1_) \
    asm volatile("mma.sync.aligned.m16n8k16.row.col.f32.f16.f16.f32 " \
        "{%0,%1,%2,%3},{%4,%5,%6,%7},{%8,%9},{%0,%1,%2,%3};" \
        : "+f"(d[0]), "+f"(d[1]), "+f"(d[2]), "+f"(d[3]) \
        : "r"(a[0]), "r"(a[1]), "r"(a[2]), "r"(a[3]), "r"(b0_), "r"(b1_))

#define LDSM4(r, addr) \
    asm volatile("ldmatrix.sync.aligned.m8n8.x4.shared.b16 {%0,%1,%2,%3}, [%4];" \
        : "=r"(r[0]), "=r"(r[1]), "=r"(r[2]), "=r"(r[3]) : "r"(addr))

__device__ __forceinline__ void cp16(uint32_t dst, const void* src) {
    asm volatile("cp.async.cg.shared.global [%0], [%1], 16;" :: "r"(dst), "l"(src));
}

__global__ void __launch_bounds__(THREADS, 1) value_model_mma_kernel(
    const float* __restrict__ state,
    const float* __restrict__ bs,
    const float* __restrict__ Wout,
    const float* __restrict__ bout,
    float* __restrict__ out)
{
    extern __shared__ char smraw[];
    __half* A = (__half*)smraw;
    const uint32_t sm_u32 = (uint32_t)__cvta_generic_to_shared(smraw);

    const int tid  = threadIdx.x;
    const int lane = tid & 31;
    const int wid  = tid >> 5;
    const int cta  = blockIdx.x;
    const int kg   = wid >> 2;         // 0..3: k-split within 8-ks chunk
    const int m    = (wid >> 1) & 1;   // row-half: rows m*32 .. m*32+31
    const int ng   = wid & 1;          // n-group: tiles ng*4 .. (<7)

    // ---- zero A plane ----
    {
        uint4 z = make_uint4(0u, 0u, 0u, 0u);
        uint4* p = (uint4*)smraw;
        for (int i = tid; i < A_BYTES / 16; i += THREADS) p[i] = z;
    }
    __syncthreads();

    // ---- initial state (64 x 16) ----
    for (int idx = tid; idx < ROWS * 16; idx += THREADS) {
        int r = idx >> 4, j = idx & 15;
        A[r * RSE + j] = __float2half_rn(state[(cta * ROWS + r) * 16 + j]);
    }
    __syncthreads();

    // ldmatrix base for this warp's two m16 tiles (rows m*32 and m*32+16)
    const uint32_t abase = sm_u32 + (uint32_t)((m * 32 + (lane & 15)) * RSE) * 2u
                                  + (uint32_t)(lane >> 4) * 16u;
    const uint32_t wsm = sm_u32 + WOFF;
    float4* scratch4 = (float4*)(smraw + WOFF);   // overlays W buffers (dead at epilogue)

    int width = 16;
    for (int l = 0; l < NLAYERS; l++) {
        const int nks = (width + 15) >> 4;
        const int nc  = (nks + 7) >> 3;

        float acc[2][4][4] = {};

        // prologue: stage chunk 0
        {
            const int ksn0 = (nks < 8) ? nks : 8;
            const char* src = (const char*)g_wfrag + (size_t)(l * MAXKS) * KSB;
            const int nops = ksn0 * 224;
            for (int i = tid; i < nops; i += THREADS) cp16(wsm + i * 16, src + i * 16);
            asm volatile("cp.async.commit_group;");
        }

        for (int c = 0; c < nc; c++) {
            if (c + 1 < nc) {
                const int rem = nks - (c + 1) * 8;
                const int ksn1 = (rem < 8) ? rem : 8;
                const char* src = (const char*)g_wfrag
                                + (size_t)(l * MAXKS + (c + 1) * 8) * KSB;
                uint32_t dst = wsm + (((c + 1) & 1) ? WBUF : 0);
                const int nops = ksn1 * 224;
                for (int i = tid; i < nops; i += THREADS) cp16(dst + i * 16, src + i * 16);
                asm volatile("cp.async.commit_group;");
                asm volatile("cp.async.wait_group 1;");
            } else {
                asm volatile("cp.async.wait_group 0;");
            }
            __syncthreads();

            const uint32_t* wb = (const uint32_t*)(smraw + WOFF + ((c & 1) ? WBUF : 0));
            const int ksn = min(8, nks - c * 8);

            #pragma unroll
            for (int i = 0; i < 2; i++) {
                const int ksl = kg * 2 + i;
                if (ksl < ksn) {
                    const int ks = c * 8 + ksl;
                    uint32_t a0[4], a1[4];
                    const uint32_t ad = abase + (uint32_t)ks * 32u;
                    LDSM4(a0, ad);
                    LDSM4(a1, ad + 16u * RSE * 2u);
                    const uint32_t* wk = wb + ksl * 896;
                    #pragma unroll
                    for (int t = 0; t < 4; t++) {
                        const int tile = ng * 4 + t;
                        if (tile < NT) {
                            const uint4 b = *(const uint4*)(wk + tile * 128 + lane * 4);
                            MMA(acc[0][t], a0, b.x, b.y);
                            MMA(acc[0][t], a0, b.z, b.w);
                            MMA(acc[1][t], a1, b.x, b.y);
                            MMA(acc[1][t], a1, b.z, b.w);
                        }
                    }
                }
            }
            __syncthreads();
        }

        // ---- epilogue: kg-reduction via scratch, bias + leaky_relu, append ----
        if (kg != 0) {
            const int slot = (kg - 1) * 4 + m * 2 + ng;
            #pragma unroll
            for (int mt = 0; mt < 2; mt++)
                #pragma unroll
                for (int t = 0; t < 4; t++)
                    scratch4[slot * 256 + (mt * 4 + t) * 32 + lane] =
                        make_float4(acc[mt][t][0], acc[mt][t][1],
                                    acc[mt][t][2], acc[mt][t][3]);
        }
        __syncthreads();
        if (kg == 0) {
            #pragma unroll
            for (int q = 0; q < 3; q++) {
                const int slot = q * 4 + m * 2 + ng;
                #pragma unroll
                for (int mt = 0; mt < 2; mt++)
                    #pragma unroll
                    for (int t = 0; t < 4; t++) {
                        float4 v = scratch4[slot * 256 + (mt * 4 + t) * 32 + lane];
                        acc[mt][t][0] += v.x; acc[mt][t][1] += v.y;
                        acc[mt][t][2] += v.z; acc[mt][t][3] += v.w;
                    }
            }
            #pragma unroll
            for (int mt = 0; mt < 2; mt++)
                #pragma unroll
                for (int t = 0; t < 4; t++) {
                    const int tile = ng * 4 + t;
                    if (tile < NT) {
                        const int n0 = tile * 8 + ((lane & 3) << 1);
                        const int rbase = m * 32 + mt * 16 + (lane >> 2);
                        #pragma unroll
                        for (int half = 0; half < 2; half++) {
                            const int n = n0 + half;
                            if (n < KOUT) {
                                const float bz = bs[l * KOUT + n];
                                #pragma unroll
                                for (int rr = 0; rr < 2; rr++) {
                                    float y = acc[mt][t][rr * 2 + half] + bz;
                                    y = (y > 0.f) ? y : 0.01f * y;
                                    A[(rbase + rr * 8) * RSE + width + n] =
                                        __float2half_rn(y);
                                }
                            }
                        }
                    }
                }
        }
        width += KOUT;
        __syncthreads();
    }

    // ---- final projection: out[r] = x . Wout + bout ----
    #pragma unroll
    for (int t = 0; t < 4; t++) {
        const int r = wid * 4 + t;
        float s = 0.f;
        for (int j = lane; j < FW; j += 32)
            s += __half2float(A[r * RSE + j]) * Wout[j];
        #pragma unroll
        for (int o = 16; o; o >>= 1) s += __shfl_xor_sync(0xffffffffu, s, o);
        if (lane == 0) out[cta * ROWS + r] = s + bout[0];
    }
}

extern "C" void kernel_launch(void* const* d_in, const int* in_sizes, int n_in,
                              void* d_out, int out_size) {
    const float* state = (const float*)d_in[0];
    const float* Ws    = (const float*)d_in[1];
    const float* bs    = (const float*)d_in[2];
    const float* Wout  = (const float*)d_in[3];
    const float* bout  = (const float*)d_in[4];
    float* out = (float*)d_out;

    const int B = in_sizes[0] / 16;   // 32768

    stage_w_kernel<<<(WFRAG_WORDS + 255) / 256, 256>>>(Ws);

    cudaFuncSetAttribute(value_model_mma_kernel,
                         cudaFuncAttributeMaxDynamicSharedMemorySize, SMEM_TOTAL);
    value_model_mma_kernel<<<B / ROWS, THREADS, SMEM_TOTAL>>>(state, bs, Wout, bout, out);
}